// round 1
// baseline (speedup 1.0000x reference)
#include <cuda_runtime.h>

// Problem constants
#define NB   2
#define NC   256
#define NSP  4096      // 16*16*16
#define NGRP 32
#define CPG  8         // channels per group

// Scratch (device globals; no allocation allowed)
__device__ float g_h[NB * NC * NSP];
__device__ float g_q[NB * NC * NSP];
__device__ float g_k[NB * NC * NSP];
__device__ float g_v[NB * NC * NSP];
__device__ float g_o[NB * NC * NSP];
__device__ float g_attn[(size_t)NB * NSP * NSP];   // 128 MiB

// ---------------------------------------------------------------------------
// GroupNorm: one block per (batch, group). Group = 8 channels x 4096 = 32768 f.
// ---------------------------------------------------------------------------
__global__ void gn_kernel(const float* __restrict__ x,
                          const float* __restrict__ w,
                          const float* __restrict__ bb,
                          float* __restrict__ h)
{
    const int b = blockIdx.x >> 5;
    const int g = blockIdx.x & 31;
    const long base = ((long)b * NC + (long)g * CPG) * NSP;
    const float* xp = x + base;
    float* hp = h + base;
    const int tid = threadIdx.x;
    const int TOT = CPG * NSP;   // 32768

    float s = 0.f, ss = 0.f;
    for (int i = tid * 4; i < TOT; i += 1024) {
        float4 v = *reinterpret_cast<const float4*>(xp + i);
        s  += v.x + v.y + v.z + v.w;
        ss += v.x * v.x + v.y * v.y + v.z * v.z + v.w * v.w;
    }

    __shared__ float rs[256], rss[256];
    rs[tid] = s; rss[tid] = ss;
    __syncthreads();
    for (int off = 128; off > 0; off >>= 1) {
        if (tid < off) { rs[tid] += rs[tid + off]; rss[tid] += rss[tid + off]; }
        __syncthreads();
    }
    const float mean = rs[0] / (float)TOT;
    const float var  = rss[0] / (float)TOT - mean * mean;
    const float inv  = rsqrtf(var + 1e-5f);

    for (int i = tid * 4; i < TOT; i += 1024) {
        const int c = g * CPG + (i >> 12);         // i / 4096 (float4 never crosses)
        const float wc = w[c] * inv;
        const float bc = bb[c] - mean * wc;
        float4 v = *reinterpret_cast<const float4*>(xp + i);
        float4 o;
        o.x = v.x * wc + bc;
        o.y = v.y * wc + bc;
        o.z = v.z * wc + bc;
        o.w = v.w * wc + bc;
        *reinterpret_cast<float4*>(hp + i) = o;
    }
}

// ---------------------------------------------------------------------------
// Row softmax over 4096 elements; one block (256 thr) per row, values held in
// registers (16 floats/thread), single read + single write of the row.
// ---------------------------------------------------------------------------
__global__ void softmax_kernel(float* __restrict__ attn)
{
    float* p = attn + (long)blockIdx.x * NSP;
    const int tid = threadIdx.x;

    float4 v[4];
    float m = -1e30f;
#pragma unroll
    for (int j = 0; j < 4; j++) {
        v[j] = *reinterpret_cast<const float4*>(p + j * 1024 + tid * 4);
        m = fmaxf(m, fmaxf(fmaxf(v[j].x, v[j].y), fmaxf(v[j].z, v[j].w)));
    }

    __shared__ float red[256];
    red[tid] = m;
    __syncthreads();
    for (int off = 128; off > 0; off >>= 1) {
        if (tid < off) red[tid] = fmaxf(red[tid], red[tid + off]);
        __syncthreads();
    }
    m = red[0];
    __syncthreads();

    float s = 0.f;
#pragma unroll
    for (int j = 0; j < 4; j++) {
        v[j].x = __expf(v[j].x - m);
        v[j].y = __expf(v[j].y - m);
        v[j].z = __expf(v[j].z - m);
        v[j].w = __expf(v[j].w - m);
        s += v[j].x + v[j].y + v[j].z + v[j].w;
    }
    red[tid] = s;
    __syncthreads();
    for (int off = 128; off > 0; off >>= 1) {
        if (tid < off) red[tid] += red[tid + off];
        __syncthreads();
    }
    const float invs = 1.f / red[0];

#pragma unroll
    for (int j = 0; j < 4; j++) {
        v[j].x *= invs; v[j].y *= invs; v[j].z *= invs; v[j].w *= invs;
        *reinterpret_cast<float4*>(p + j * 1024 + tid * 4) = v[j];
    }
}

// ---------------------------------------------------------------------------
// Generic 128x128x8 register-blocked SGEMM.
//   TA=0: A is M x K row-major       (A[m*K + k])
//   TA=1: A is stored K-major        (A[k*M + m])
//   TB=0: B is K x N row-major       (B[k*N + n])
//   TB=1: B is stored N x K          (B[n*K + k])
// C[m,n] = alpha * sum_k A.B   (+ bias[m]) (+ resid[m,n])
// Requires M,N % 128 == 0, K % 8 == 0 (true for all uses here).
// ---------------------------------------------------------------------------
template<int TA, int TB>
__global__ __launch_bounds__(256)
void sgemm_kernel(const float* __restrict__ A,
                  const float* __restrict__ Bm,
                  float* __restrict__ Cm,
                  int M, int N, int K,
                  long sA, long sB, long sC,
                  const float* __restrict__ bias,
                  const float* __restrict__ resid, long sR,
                  float alpha)
{
    __shared__ float As[8][128];
    __shared__ float Bs[8][128];

    const int tid = threadIdx.x;
    const int bm = blockIdx.y * 128;
    const int bn = blockIdx.x * 128;
    const int bz = blockIdx.z;

    const float* Ap = A  + (long)bz * sA;
    const float* Bp = Bm + (long)bz * sB;

    float acc[8][8] = {};
    const int ty = tid >> 4;     // 0..15
    const int tx = tid & 15;     // 0..15

    for (int k0 = 0; k0 < K; k0 += 8) {
        if (TA == 0) {
            const int ar = tid >> 1;            // m within tile
            const int ac = (tid & 1) << 2;      // k within tile
            float4 a = *reinterpret_cast<const float4*>(Ap + (long)(bm + ar) * K + k0 + ac);
            As[ac + 0][ar] = a.x; As[ac + 1][ar] = a.y;
            As[ac + 2][ar] = a.z; As[ac + 3][ar] = a.w;
        } else {
            const int ar = tid >> 5;            // k within tile
            const int ac = (tid & 31) << 2;     // m within tile
            float4 a = *reinterpret_cast<const float4*>(Ap + (long)(k0 + ar) * M + bm + ac);
            *reinterpret_cast<float4*>(&As[ar][ac]) = a;
        }
        if (TB == 0) {
            const int br = tid >> 5;            // k
            const int bc = (tid & 31) << 2;     // n
            float4 v = *reinterpret_cast<const float4*>(Bp + (long)(k0 + br) * N + bn + bc);
            *reinterpret_cast<float4*>(&Bs[br][bc]) = v;
        } else {
            const int br = tid >> 1;            // n
            const int bc = (tid & 1) << 2;      // k
            float4 v = *reinterpret_cast<const float4*>(Bp + (long)(bn + br) * K + k0 + bc);
            Bs[bc + 0][br] = v.x; Bs[bc + 1][br] = v.y;
            Bs[bc + 2][br] = v.z; Bs[bc + 3][br] = v.w;
        }
        __syncthreads();

#pragma unroll
        for (int kk = 0; kk < 8; kk++) {
            float af[8], bf[8];
#pragma unroll
            for (int i = 0; i < 8; i++) af[i] = As[kk][ty * 8 + i];
#pragma unroll
            for (int j = 0; j < 8; j++) bf[j] = Bs[kk][tx * 8 + j];
#pragma unroll
            for (int i = 0; i < 8; i++)
#pragma unroll
                for (int j = 0; j < 8; j++)
                    acc[i][j] += af[i] * bf[j];
        }
        __syncthreads();
    }

    float* Cp = Cm + (long)bz * sC;
#pragma unroll
    for (int i = 0; i < 8; i++) {
        const int row = bm + ty * 8 + i;
        const float bv = bias ? bias[row] : 0.f;
#pragma unroll
        for (int j = 0; j < 8; j += 4) {
            const int col = bn + tx * 8 + j;
            float4 o;
            o.x = acc[i][j + 0] * alpha + bv;
            o.y = acc[i][j + 1] * alpha + bv;
            o.z = acc[i][j + 2] * alpha + bv;
            o.w = acc[i][j + 3] * alpha + bv;
            if (resid) {
                float4 r = *reinterpret_cast<const float4*>(resid + (long)bz * sR + (long)row * N + col);
                o.x += r.x; o.y += r.y; o.z += r.z; o.w += r.w;
            }
            *reinterpret_cast<float4*>(Cp + (long)row * N + col) = o;
        }
    }
}

// ---------------------------------------------------------------------------
extern "C" void kernel_launch(void* const* d_in, const int* in_sizes, int n_in,
                              void* d_out, int out_size)
{
    const float* x   = (const float*)d_in[0];
    const float* gnw = (const float*)d_in[1];
    const float* gnb = (const float*)d_in[2];
    const float* wq  = (const float*)d_in[3];
    const float* bq  = (const float*)d_in[4];
    const float* wk  = (const float*)d_in[5];
    const float* bk  = (const float*)d_in[6];
    const float* wv  = (const float*)d_in[7];
    const float* bv  = (const float*)d_in[8];
    const float* wp  = (const float*)d_in[9];
    const float* bp  = (const float*)d_in[10];
    float* out = (float*)d_out;

    float *h, *q, *k, *v, *o, *attn;
    cudaGetSymbolAddress((void**)&h,    g_h);
    cudaGetSymbolAddress((void**)&q,    g_q);
    cudaGetSymbolAddress((void**)&k,    g_k);
    cudaGetSymbolAddress((void**)&v,    g_v);
    cudaGetSymbolAddress((void**)&o,    g_o);
    cudaGetSymbolAddress((void**)&attn, g_attn);

    const long sCN = (long)NC * NSP;        // per-batch stride of (C,N) tensors
    const long sNN = (long)NSP * NSP;       // per-batch stride of attn

    // 1) GroupNorm
    gn_kernel<<<NB * NGRP, 256>>>(x, gnw, gnb, h);

    // 2) q, k, v projections: (256 x 256) @ (256 x 4096)
    dim3 gP(NSP / 128, NC / 128, NB);       // 32 x 2 x 2
    sgemm_kernel<0, 0><<<gP, 256>>>(wq, h, q, NC, NSP, NC, 0, sCN, sCN, bq, nullptr, 0, 1.f);
    sgemm_kernel<0, 0><<<gP, 256>>>(wk, h, k, NC, NSP, NC, 0, sCN, sCN, bk, nullptr, 0, 1.f);
    sgemm_kernel<0, 0><<<gP, 256>>>(wv, h, v, NC, NSP, NC, 0, sCN, sCN, bv, nullptr, 0, 1.f);

    // 3) scores: attn[n,m] = scale * sum_c q[c,n] k[c,m]   (TN GEMM)
    dim3 gS(NSP / 128, NSP / 128, NB);      // 32 x 32 x 2
    sgemm_kernel<1, 0><<<gS, 256>>>(q, k, attn, NSP, NSP, NC, sCN, sCN, sNN,
                                    nullptr, nullptr, 0, 0.0625f);

    // 4) softmax over last axis
    softmax_kernel<<<NB * NSP, 256>>>(attn);

    // 5) out[c,n] = sum_m v[c,m] * p[n,m]   (NT GEMM)
    sgemm_kernel<0, 1><<<gP, 256>>>(v, attn, o, NC, NSP, NSP, sCN, sNN, sCN,
                                    nullptr, nullptr, 0, 1.f);

    // 6) projection + residual: y = x + wp @ o + bp
    sgemm_kernel<0, 0><<<gP, 256>>>(wp, o, out, NC, NSP, NC, 0, sCN, sCN,
                                    bp, x, sCN, 1.f);
}

// round 5
// speedup vs baseline: 3.1354x; 3.1354x over previous
#include <cuda_runtime.h>
#include <cstdint>

#define NB   2
#define NC   256
#define NSP  4096
#define NGRP 32
#define CPG  8

// ---------------- scratch (no allocation allowed) ----------------
__device__ float g_ht  [(size_t)NB * NC * NSP];   // hT  [b][n][c]
__device__ float g_qt  [(size_t)NB * NC * NSP];   // qT  [b][n][o]  (pre-scaled by 1/16)
__device__ float g_kt  [(size_t)NB * NC * NSP];   // kT  [b][n][o]
__device__ float g_v   [(size_t)NB * NC * NSP];   // v   [b][o][m]
__device__ float g_ot  [(size_t)NB * NC * NSP];   // outT[b][n][o]
__device__ float g_attn[(size_t)NB * NSP * NSP];  // 128 MiB
__device__ float g_stat[NB * NGRP * 2];

// ---------------- helpers ----------------
__device__ __forceinline__ float tf32r(float x) {
    uint32_t y;
    asm("cvt.rna.tf32.f32 %0, %1;" : "=r"(y) : "f"(x));
    return __uint_as_float(y);
}

__device__ __forceinline__ void mma8(float* c, const uint32_t* a, const uint32_t* b) {
    asm volatile(
        "mma.sync.aligned.m16n8k8.row.col.f32.tf32.tf32.f32 "
        "{%0,%1,%2,%3}, {%4,%5,%6,%7}, {%8,%9}, {%0,%1,%2,%3};\n"
        : "+f"(c[0]), "+f"(c[1]), "+f"(c[2]), "+f"(c[3])
        : "r"(a[0]), "r"(a[1]), "r"(a[2]), "r"(a[3]),
          "r"(b[0]), "r"(b[1]));
}

// ---------------- GroupNorm stats ----------------
__global__ void gn_stats(const float* __restrict__ x, float* __restrict__ stat)
{
    const int b = blockIdx.x >> 5;
    const int g = blockIdx.x & 31;
    const float* xp = x + ((long)b * NC + (long)g * CPG) * NSP;
    const int tid = threadIdx.x;
    const int TOT = CPG * NSP;

    float s = 0.f, ss = 0.f;
    for (int i = tid * 4; i < TOT; i += 1024) {
        float4 v = *reinterpret_cast<const float4*>(xp + i);
        s  += v.x + v.y + v.z + v.w;
        ss += v.x * v.x + v.y * v.y + v.z * v.z + v.w * v.w;
    }
    __shared__ float rs[256], rss[256];
    rs[tid] = s; rss[tid] = ss;
    __syncthreads();
    for (int off = 128; off > 0; off >>= 1) {
        if (tid < off) { rs[tid] += rs[tid + off]; rss[tid] += rss[tid + off]; }
        __syncthreads();
    }
    if (tid == 0) {
        float mean = rs[0] / (float)TOT;
        float var  = rss[0] / (float)TOT - mean * mean;
        stat[blockIdx.x * 2 + 0] = mean;
        stat[blockIdx.x * 2 + 1] = rsqrtf(var + 1e-5f);
    }
}

// ---------------- GroupNorm apply + transpose: x[b][c][n] -> ht[b][n][c] ----
__global__ void gn_apply(const float* __restrict__ x,
                         const float* __restrict__ w,
                         const float* __restrict__ bb,
                         const float* __restrict__ stat,
                         float* __restrict__ ht)
{
    __shared__ float t[32][33];
    const int b  = blockIdx.z;
    const int c0 = blockIdx.x * 32;
    const int n0 = blockIdx.y * 32;
    const int tx = threadIdx.x, ty = threadIdx.y;
    const float* xb = x  + (long)b * NC * NSP;
    float*       hb = ht + (long)b * NSP * NC;

#pragma unroll
    for (int j = 0; j < 4; j++) {
        const int c = c0 + ty + j * 8;
        const int g = c >> 3;
        const float mean = stat[(b * NGRP + g) * 2 + 0];
        const float inv  = stat[(b * NGRP + g) * 2 + 1];
        const float wc = w[c] * inv;
        const float bc = bb[c] - mean * wc;
        t[ty + j * 8][tx] = xb[(long)c * NSP + n0 + tx] * wc + bc;
    }
    __syncthreads();
#pragma unroll
    for (int j = 0; j < 4; j++) {
        const int n = n0 + ty + j * 8;
        hb[(long)n * NC + c0 + tx] = t[tx][ty + j * 8];
    }
}

// ---------------- row softmax over 4096 ----------------
__global__ void softmax_kernel(float* __restrict__ attn)
{
    float* p = attn + (long)blockIdx.x * NSP;
    const int tid = threadIdx.x;

    float4 v[4];
    float m = -1e30f;
#pragma unroll
    for (int j = 0; j < 4; j++) {
        v[j] = *reinterpret_cast<const float4*>(p + j * 1024 + tid * 4);
        m = fmaxf(m, fmaxf(fmaxf(v[j].x, v[j].y), fmaxf(v[j].z, v[j].w)));
    }
    __shared__ float red[256];
    red[tid] = m; __syncthreads();
    for (int off = 128; off > 0; off >>= 1) {
        if (tid < off) red[tid] = fmaxf(red[tid], red[tid + off]);
        __syncthreads();
    }
    m = red[0]; __syncthreads();

    float s = 0.f;
#pragma unroll
    for (int j = 0; j < 4; j++) {
        v[j].x = __expf(v[j].x - m); v[j].y = __expf(v[j].y - m);
        v[j].z = __expf(v[j].z - m); v[j].w = __expf(v[j].w - m);
        s += v[j].x + v[j].y + v[j].z + v[j].w;
    }
    red[tid] = s; __syncthreads();
    for (int off = 128; off > 0; off >>= 1) {
        if (tid < off) red[tid] += red[tid + off];
        __syncthreads();
    }
    const float invs = 1.f / red[0];
#pragma unroll
    for (int j = 0; j < 4; j++) {
        v[j].x *= invs; v[j].y *= invs; v[j].z *= invs; v[j].w *= invs;
        *reinterpret_cast<float4*>(p + j * 1024 + tid * 4) = v[j];
    }
}

// ---------------------------------------------------------------------------
// tf32 GEMM via explicit PTX mma.sync.m16n8k8.
//   C[m,n] = (sum_k A[m,k]*B[n,k] + bias) * alpha (+ resid)
//   A: M x K row-major (lda);  B: N x K k-contiguous (ldb);  C row-major (ldc).
// CTA 128x128x(BK=32), 256 thr = 8 warps (2m x 4n), warp tile 64x32.
// smem stride 36: scalar fragment loads are bank-conflict-free (bank = 4g+t).
// Requires M,N % 128 == 0, K % 32 == 0.
// ---------------------------------------------------------------------------
#define TSZ (128 * 36)

template<int BIASCOL, int HASRES>
__global__ __launch_bounds__(256)
void mma_gemm(const float* __restrict__ A, long sA, int lda,
              const float* __restrict__ B, long sB, int ldb,
              float* __restrict__ C, long sC, int ldc,
              int K, float alpha,
              const float* __restrict__ bias,
              const float* __restrict__ resid, long sR)
{
    extern __shared__ float sm[];
    const int tid = threadIdx.x;
    const int wid = tid >> 5, lane = tid & 31;
    const int wm = wid >> 2, wn = wid & 3;
    const int g = lane >> 2, t = lane & 3;
    const int bz = blockIdx.z;
    const long bm = (long)blockIdx.y * 128;
    const long bn = (long)blockIdx.x * 128;

    const int rr = tid >> 3, ii = tid & 7;
    const float* gA = A + (long)bz * sA + (bm + rr) * lda + ii * 4;
    const float* gB = B + (long)bz * sB + (bn + rr) * ldb + ii * 4;

    float c[4][4][4];
#pragma unroll
    for (int mi = 0; mi < 4; mi++)
#pragma unroll
        for (int ni = 0; ni < 4; ni++)
#pragma unroll
            for (int j = 0; j < 4; j++) c[mi][ni][j] = 0.f;

    float4 ra[4], rb[4];

#define LDG_TILES(k0) do { \
    _Pragma("unroll") for (int r = 0; r < 4; r++) \
        ra[r] = *reinterpret_cast<const float4*>(gA + (long)(k0) + 32L * r * lda); \
    _Pragma("unroll") for (int r = 0; r < 4; r++) \
        rb[r] = *reinterpret_cast<const float4*>(gB + (long)(k0) + 32L * r * ldb); \
} while (0)

#define STS_TILES(buf) do { \
    float* As_ = sm + (buf) * TSZ + rr * 36 + ii * 4; \
    float* Bs_ = sm + 2 * TSZ + (buf) * TSZ + rr * 36 + ii * 4; \
    _Pragma("unroll") for (int r = 0; r < 4; r++) { \
        float4 v4 = ra[r]; \
        v4.x = tf32r(v4.x); v4.y = tf32r(v4.y); v4.z = tf32r(v4.z); v4.w = tf32r(v4.w); \
        *reinterpret_cast<float4*>(As_ + r * 32 * 36) = v4; } \
    _Pragma("unroll") for (int r = 0; r < 4; r++) { \
        float4 v4 = rb[r]; \
        v4.x = tf32r(v4.x); v4.y = tf32r(v4.y); v4.z = tf32r(v4.z); v4.w = tf32r(v4.w); \
        *reinterpret_cast<float4*>(Bs_ + r * 32 * 36) = v4; } \
} while (0)

    const int nIter = K >> 5;
    LDG_TILES(0);
    STS_TILES(0);
    __syncthreads();

    for (int it = 0; it < nIter; ++it) {
        const int buf = it & 1;
        if (it + 1 < nIter) LDG_TILES((it + 1) * 32);

        const float* As = sm + buf * TSZ + (wm * 64 + g) * 36;
        const float* Bs = sm + 2 * TSZ + buf * TSZ + (wn * 32 + g) * 36;

#pragma unroll
        for (int kk = 0; kk < 32; kk += 8) {
            uint32_t a[4][4], b[4][2];
#pragma unroll
            for (int mi = 0; mi < 4; mi++) {
                const float* ap = As + mi * 16 * 36 + kk + t;
                a[mi][0] = __float_as_uint(ap[0]);
                a[mi][1] = __float_as_uint(ap[8 * 36]);
                a[mi][2] = __float_as_uint(ap[4]);
                a[mi][3] = __float_as_uint(ap[8 * 36 + 4]);
            }
#pragma unroll
            for (int ni = 0; ni < 4; ni++) {
                const float* bp = Bs + ni * 8 * 36 + kk + t;
                b[ni][0] = __float_as_uint(bp[0]);
                b[ni][1] = __float_as_uint(bp[4]);
            }
#pragma unroll
            for (int mi = 0; mi < 4; mi++)
#pragma unroll
                for (int ni = 0; ni < 4; ni++)
                    mma8(c[mi][ni], a[mi], b[ni]);
        }

        if (it + 1 < nIter) STS_TILES(buf ^ 1);
        __syncthreads();
    }

    // ---------------- register-resident epilogue ----------------
    float* Cz = C + (long)bz * sC;
    const float* Rz = HASRES ? (resid + (long)bz * sR) : nullptr;

#pragma unroll
    for (int mi = 0; mi < 4; mi++) {
        const long row0 = bm + wm * 64 + mi * 16 + g;
        const long row1 = row0 + 8;
        float br0 = 0.f, br1 = 0.f;
        if (!BIASCOL && bias) { br0 = bias[row0]; br1 = bias[row1]; }
#pragma unroll
        for (int ni = 0; ni < 4; ni++) {
            const long col = bn + wn * 32 + ni * 8 + 2 * t;
            float2 v0 = make_float2(c[mi][ni][0], c[mi][ni][1]);
            float2 v1 = make_float2(c[mi][ni][2], c[mi][ni][3]);
            if (BIASCOL) {
                const float bc0 = bias[col], bc1 = bias[col + 1];
                v0.x += bc0; v0.y += bc1; v1.x += bc0; v1.y += bc1;
            } else if (bias) {
                v0.x += br0; v0.y += br0; v1.x += br1; v1.y += br1;
            }
            v0.x *= alpha; v0.y *= alpha; v1.x *= alpha; v1.y *= alpha;
            if (HASRES) {
                float2 r0 = *reinterpret_cast<const float2*>(Rz + row0 * ldc + col);
                float2 r1 = *reinterpret_cast<const float2*>(Rz + row1 * ldc + col);
                v0.x += r0.x; v0.y += r0.y; v1.x += r1.x; v1.y += r1.y;
            }
            *reinterpret_cast<float2*>(Cz + row0 * ldc + col) = v0;
            *reinterpret_cast<float2*>(Cz + row1 * ldc + col) = v1;
        }
    }
#undef LDG_TILES
#undef STS_TILES
}

// ---------------------------------------------------------------------------
extern "C" void kernel_launch(void* const* d_in, const int* in_sizes, int n_in,
                              void* d_out, int out_size)
{
    const float* x   = (const float*)d_in[0];
    const float* gnw = (const float*)d_in[1];
    const float* gnb = (const float*)d_in[2];
    const float* wq  = (const float*)d_in[3];
    const float* bq  = (const float*)d_in[4];
    const float* wk  = (const float*)d_in[5];
    const float* bk  = (const float*)d_in[6];
    const float* wv  = (const float*)d_in[7];
    const float* bv  = (const float*)d_in[8];
    const float* wp  = (const float*)d_in[9];
    const float* bp  = (const float*)d_in[10];
    float* out = (float*)d_out;

    float *ht, *qt, *kt, *v, *ot, *attn, *stat;
    cudaGetSymbolAddress((void**)&ht,   g_ht);
    cudaGetSymbolAddress((void**)&qt,   g_qt);
    cudaGetSymbolAddress((void**)&kt,   g_kt);
    cudaGetSymbolAddress((void**)&v,    g_v);
    cudaGetSymbolAddress((void**)&ot,   g_ot);
    cudaGetSymbolAddress((void**)&attn, g_attn);
    cudaGetSymbolAddress((void**)&stat, g_stat);

    const long sCN = (long)NC * NSP;
    const long sNN = (long)NSP * NSP;
    const int SMEM = 4 * TSZ * 4;   // 73728 bytes

    cudaFuncSetAttribute(mma_gemm<1, 0>, cudaFuncAttributeMaxDynamicSharedMemorySize, SMEM);
    cudaFuncSetAttribute(mma_gemm<0, 0>, cudaFuncAttributeMaxDynamicSharedMemorySize, SMEM);
    cudaFuncSetAttribute(mma_gemm<0, 1>, cudaFuncAttributeMaxDynamicSharedMemorySize, SMEM);

    // 1) GroupNorm -> ht[b][n][c]
    gn_stats<<<NB * NGRP, 256>>>(x, stat);
    gn_apply<<<dim3(NC / 32, NSP / 32, NB), dim3(32, 8)>>>(x, gnw, gnb, stat, ht);

    // 2) q: qt[n][o] = (ht[n][:] . wq[o][:] + bq[o]) / 16   (scale folded in)
    dim3 gQ(NC / 128, NSP / 128, NB);       // 2 x 32 x 2
    mma_gemm<1, 0><<<gQ, 256, SMEM>>>(ht, sCN, NC, wq, 0, NC, qt, sCN, NC,
                                      NC, 0.0625f, bq, nullptr, 0);
    //    k: kt[n][o]
    mma_gemm<1, 0><<<gQ, 256, SMEM>>>(ht, sCN, NC, wk, 0, NC, kt, sCN, NC,
                                      NC, 1.f, bk, nullptr, 0);
    //    v: v[o][m] = wv[o][:] . ht[m][:] + bv[o]
    dim3 gV(NSP / 128, NC / 128, NB);       // 32 x 2 x 2
    mma_gemm<0, 0><<<gV, 256, SMEM>>>(wv, 0, NC, ht, sCN, NC, v, sCN, NSP,
                                      NC, 1.f, bv, nullptr, 0);

    // 3) logits: attn[n][m] = qt[n][:] . kt[m][:]
    dim3 gS(NSP / 128, NSP / 128, NB);      // 32 x 32 x 2
    mma_gemm<0, 0><<<gS, 256, SMEM>>>(qt, sCN, NC, kt, sCN, NC, attn, sNN, NSP,
                                      NC, 1.f, nullptr, nullptr, 0);

    // 4) softmax rows
    softmax_kernel<<<NB * NSP, 256>>>(attn);

    // 5) ot[n][o] = attn[n][:] . v[o][:]
    dim3 gO(NC / 128, NSP / 128, NB);       // 2 x 32 x 2
    mma_gemm<0, 0><<<gO, 256, SMEM>>>(attn, sNN, NSP, v, sCN, NSP, ot, sCN, NC,
                                      NSP, 1.f, nullptr, nullptr, 0);

    // 6) y[o][n] = wp[o][:] . ot[n][:] + bp[o] + x
    mma_gemm<0, 1><<<gV, 256, SMEM>>>(wp, 0, NC, ot, sCN, NC, out, sCN, NSP,
                                      NC, 1.f, bp, x, sCN);
}